// round 1
// baseline (speedup 1.0000x reference)
#include <cuda_runtime.h>
#include <math.h>

#define NTOK 32768
#define DDIM 256
#define EEXP 8
#define HDIM 1024
#define MAXENT (NTOK * 2)

// ---------------- static device scratch (no allocations) ----------------
__device__ float g_h [(size_t)MAXENT * HDIM];   // gelu(x@W1+b1) rows, compacted
__device__ float g_yp[(size_t)MAXENT * DDIM];   // weighted expert outputs per (token,slot)
__device__ int   g_idx[EEXP * NTOK];            // (token<<1)|slot per expert list
__device__ float g_w  [EEXP * NTOK];            // gate weight per list entry
__device__ int   g_cnt[EEXP];
__device__ int   g_off[EEXP];

__device__ __forceinline__ float gelu_exact(float v) {
    return 0.5f * v * (1.0f + erff(v * 0.70710678118654752440f));
}

// ---------------- phase 0: reset counters ----------------
__global__ void zero_cnt_kernel() {
    if (threadIdx.x < EEXP) g_cnt[threadIdx.x] = 0;
}

// ---------------- phase 1: router (warp per token) ----------------
__global__ void router_kernel(const float* __restrict__ x,
                              const float* __restrict__ grad,
                              const float* __restrict__ Wr,
                              const float* __restrict__ br,
                              float* __restrict__ probs_out) {
    __shared__ float sWr[(DDIM + 1) * EEXP];
    __shared__ float sbr[EEXP];
    const int tid = threadIdx.x;
    for (int i = tid; i < (DDIM + 1) * EEXP; i += blockDim.x) sWr[i] = Wr[i];
    if (tid < EEXP) sbr[tid] = br[tid];
    __syncthreads();

    const int warp = tid >> 5, lane = tid & 31;
    const int n = blockIdx.x * 8 + warp;

    float acc[EEXP];
#pragma unroll
    for (int e = 0; e < EEXP; e++) acc[e] = 0.f;

    const float* xr = x + (size_t)n * DDIM;
#pragma unroll
    for (int it = 0; it < DDIM / 32; it++) {
        const int d = it * 32 + lane;
        const float xv = xr[d];
#pragma unroll
        for (int e = 0; e < EEXP; e++) acc[e] += xv * sWr[d * EEXP + e];
    }
#pragma unroll
    for (int e = 0; e < EEXP; e++) {
        float v = acc[e];
#pragma unroll
        for (int o = 16; o > 0; o >>= 1) v += __shfl_xor_sync(0xffffffffu, v, o);
        acc[e] = v;
    }
    if (lane == 0) {
        const float g = grad[n];
        float mx = -1e30f;
#pragma unroll
        for (int e = 0; e < EEXP; e++) {
            acc[e] += g * sWr[DDIM * EEXP + e] + sbr[e];
            mx = fmaxf(mx, acc[e]);
        }
        float s = 0.f;
#pragma unroll
        for (int e = 0; e < EEXP; e++) { acc[e] = expf(acc[e] - mx); s += acc[e]; }
        const float inv = 1.f / s;
#pragma unroll
        for (int e = 0; e < EEXP; e++) {
            acc[e] *= inv;
            probs_out[(size_t)n * EEXP + e] = acc[e];
        }
        // top-2 (ties -> lowest index, matching lax.top_k)
        int e0 = 0;
#pragma unroll
        for (int e = 1; e < EEXP; e++) if (acc[e] > acc[e0]) e0 = e;
        int e1 = (e0 == 0) ? 1 : 0;
#pragma unroll
        for (int e = 0; e < EEXP; e++) if (e != e0 && acc[e] > acc[e1]) e1 = e;

        int p0 = atomicAdd(&g_cnt[e0], 1);
        g_idx[e0 * NTOK + p0] = (n << 1);
        g_w  [e0 * NTOK + p0] = acc[e0];
        int p1 = atomicAdd(&g_cnt[e1], 1);
        g_idx[e1 * NTOK + p1] = (n << 1) | 1;
        g_w  [e1 * NTOK + p1] = acc[e1];
    }
}

// ---------------- phase 2: exclusive prefix over counts ----------------
__global__ void offsets_kernel() {
    if (threadIdx.x == 0) {
        int s = 0;
        for (int e = 0; e < EEXP; e++) { g_off[e] = s; s += g_cnt[e]; }
    }
}

// ---------------- phase 3: GEMM1  h = gelu(gather(x) @ W1[e] + b1[e]) ----------------
// 128x128 tile, BK=8, 256 threads, 8x8 microtile
__global__ __launch_bounds__(256, 2)
void gemm1_kernel(const float* __restrict__ x,
                  const float* __restrict__ W1,
                  const float* __restrict__ b1) {
    const int e = blockIdx.z;
    const int cnt = g_cnt[e];
    const int m0 = blockIdx.y * 128;
    if (m0 >= cnt) return;
    const int n0 = blockIdx.x * 128;
    const int off = g_off[e];
    const int mRem = cnt - m0;

    __shared__ float As[8][128];
    __shared__ float Bs[8][128];

    const int tid  = threadIdx.x;
    const int aRow = tid >> 1;
    const int aK   = (tid & 1) << 2;
    const int bK   = tid >> 5;
    const int bCol = (tid & 31) << 2;
    const int trow = (tid >> 4) << 3;
    const int tcol = (tid & 15) << 3;

    const float* Aptr = nullptr;
    if (aRow < mRem) {
        const int ent = g_idx[e * NTOK + m0 + aRow];
        Aptr = x + (size_t)(ent >> 1) * DDIM + aK;
    }
    const float* Bptr = W1 + (size_t)e * DDIM * HDIM + (size_t)bK * HDIM + n0 + bCol;

    float acc[8][8];
#pragma unroll
    for (int i = 0; i < 8; i++)
#pragma unroll
        for (int j = 0; j < 8; j++) acc[i][j] = 0.f;

    float4 aF = Aptr ? *(const float4*)Aptr : make_float4(0.f, 0.f, 0.f, 0.f);
    float4 bF = *(const float4*)Bptr;

    for (int k0 = 0; k0 < DDIM; k0 += 8) {
        As[aK + 0][aRow] = aF.x;
        As[aK + 1][aRow] = aF.y;
        As[aK + 2][aRow] = aF.z;
        As[aK + 3][aRow] = aF.w;
        *(float4*)&Bs[bK][bCol] = bF;
        __syncthreads();

        if (k0 + 8 < DDIM) {
            aF = Aptr ? *(const float4*)(Aptr + k0 + 8) : make_float4(0.f, 0.f, 0.f, 0.f);
            bF = *(const float4*)(Bptr + (size_t)(k0 + 8) * HDIM);
        }
#pragma unroll
        for (int kk = 0; kk < 8; kk++) {
            float a[8], b[8];
            *(float4*)&a[0] = *(const float4*)&As[kk][trow];
            *(float4*)&a[4] = *(const float4*)&As[kk][trow + 4];
            *(float4*)&b[0] = *(const float4*)&Bs[kk][tcol];
            *(float4*)&b[4] = *(const float4*)&Bs[kk][tcol + 4];
#pragma unroll
            for (int i = 0; i < 8; i++)
#pragma unroll
                for (int j = 0; j < 8; j++) acc[i][j] += a[i] * b[j];
        }
        __syncthreads();
    }

    float bias[8];
#pragma unroll
    for (int j = 0; j < 8; j++) bias[j] = b1[e * HDIM + n0 + tcol + j];

#pragma unroll
    for (int i = 0; i < 8; i++) {
        const int m = trow + i;
        if (m < mRem) {
            float* dst = g_h + (size_t)(off + m0 + m) * HDIM + n0 + tcol;
            float4 v0, v1;
            v0.x = gelu_exact(acc[i][0] + bias[0]);
            v0.y = gelu_exact(acc[i][1] + bias[1]);
            v0.z = gelu_exact(acc[i][2] + bias[2]);
            v0.w = gelu_exact(acc[i][3] + bias[3]);
            v1.x = gelu_exact(acc[i][4] + bias[4]);
            v1.y = gelu_exact(acc[i][5] + bias[5]);
            v1.z = gelu_exact(acc[i][6] + bias[6]);
            v1.w = gelu_exact(acc[i][7] + bias[7]);
            *(float4*)dst       = v0;
            *(float4*)(dst + 4) = v1;
        }
    }
}

// ---------------- phase 4: GEMM2  yp = w * (h @ W2[e] + b2[e]) ----------------
__global__ __launch_bounds__(256, 2)
void gemm2_kernel(const float* __restrict__ W2,
                  const float* __restrict__ b2) {
    const int e = blockIdx.z;
    const int cnt = g_cnt[e];
    const int m0 = blockIdx.y * 128;
    if (m0 >= cnt) return;
    const int n0 = blockIdx.x * 128;
    const int off = g_off[e];
    const int mRem = cnt - m0;

    __shared__ float As[8][128];
    __shared__ float Bs[8][128];

    const int tid  = threadIdx.x;
    const int aRow = tid >> 1;
    const int aK   = (tid & 1) << 2;
    const int bK   = tid >> 5;
    const int bCol = (tid & 31) << 2;
    const int trow = (tid >> 4) << 3;
    const int tcol = (tid & 15) << 3;

    const float* Aptr = (aRow < mRem)
        ? g_h + (size_t)(off + m0 + aRow) * HDIM + aK
        : nullptr;
    const float* Bptr = W2 + (size_t)e * HDIM * DDIM + (size_t)bK * DDIM + n0 + bCol;

    float acc[8][8];
#pragma unroll
    for (int i = 0; i < 8; i++)
#pragma unroll
        for (int j = 0; j < 8; j++) acc[i][j] = 0.f;

    float4 aF = Aptr ? *(const float4*)Aptr : make_float4(0.f, 0.f, 0.f, 0.f);
    float4 bF = *(const float4*)Bptr;

    for (int k0 = 0; k0 < HDIM; k0 += 8) {
        As[aK + 0][aRow] = aF.x;
        As[aK + 1][aRow] = aF.y;
        As[aK + 2][aRow] = aF.z;
        As[aK + 3][aRow] = aF.w;
        *(float4*)&Bs[bK][bCol] = bF;
        __syncthreads();

        if (k0 + 8 < HDIM) {
            aF = Aptr ? *(const float4*)(Aptr + k0 + 8) : make_float4(0.f, 0.f, 0.f, 0.f);
            bF = *(const float4*)(Bptr + (size_t)(k0 + 8) * DDIM);
        }
#pragma unroll
        for (int kk = 0; kk < 8; kk++) {
            float a[8], b[8];
            *(float4*)&a[0] = *(const float4*)&As[kk][trow];
            *(float4*)&a[4] = *(const float4*)&As[kk][trow + 4];
            *(float4*)&b[0] = *(const float4*)&Bs[kk][tcol];
            *(float4*)&b[4] = *(const float4*)&Bs[kk][tcol + 4];
#pragma unroll
            for (int i = 0; i < 8; i++)
#pragma unroll
                for (int j = 0; j < 8; j++) acc[i][j] += a[i] * b[j];
        }
        __syncthreads();
    }

    float bias[8];
#pragma unroll
    for (int j = 0; j < 8; j++) bias[j] = b2[e * DDIM + n0 + tcol + j];

#pragma unroll
    for (int i = 0; i < 8; i++) {
        const int m = trow + i;
        if (m < mRem) {
            const int ent = g_idx[e * NTOK + m0 + m];
            const float w = g_w[e * NTOK + m0 + m];
            float* dst = g_yp + (size_t)ent * DDIM + n0 + tcol;
            float4 v0, v1;
            v0.x = w * (acc[i][0] + bias[0]);
            v0.y = w * (acc[i][1] + bias[1]);
            v0.z = w * (acc[i][2] + bias[2]);
            v0.w = w * (acc[i][3] + bias[3]);
            v1.x = w * (acc[i][4] + bias[4]);
            v1.y = w * (acc[i][5] + bias[5]);
            v1.z = w * (acc[i][6] + bias[6]);
            v1.w = w * (acc[i][7] + bias[7]);
            *(float4*)dst       = v0;
            *(float4*)(dst + 4) = v1;
        }
    }
}

// ---------------- phase 5: combine the two weighted slots per token ----------------
__global__ void combine_kernel(float* __restrict__ out) {
    const int i = blockIdx.x * blockDim.x + threadIdx.x;   // over N*D/4 float4s
    const int n  = i / (DDIM / 4);
    const int d4 = i % (DDIM / 4);
    const float4* yp4 = (const float4*)g_yp;
    const float4 u = yp4[(size_t)n * (2 * DDIM / 4) + d4];
    const float4 v = yp4[(size_t)n * (2 * DDIM / 4) + (DDIM / 4) + d4];
    float4 r;
    r.x = u.x + v.x; r.y = u.y + v.y; r.z = u.z + v.z; r.w = u.w + v.w;
    ((float4*)out)[i] = r;
}

// ---------------- launch ----------------
extern "C" void kernel_launch(void* const* d_in, const int* in_sizes, int n_in,
                              void* d_out, int out_size) {
    const float* x    = (const float*)d_in[0];
    const float* grad = (const float*)d_in[1];
    const float* Wr   = (const float*)d_in[2];
    const float* br   = (const float*)d_in[3];
    const float* W1   = (const float*)d_in[4];
    const float* b1   = (const float*)d_in[5];
    const float* W2   = (const float*)d_in[6];
    const float* b2   = (const float*)d_in[7];
    float* out   = (float*)d_out;
    float* probs = out + (size_t)NTOK * DDIM;

    zero_cnt_kernel<<<1, 32>>>();
    router_kernel<<<NTOK / 8, 256>>>(x, grad, Wr, br, probs);
    offsets_kernel<<<1, 32>>>();
    gemm1_kernel<<<dim3(HDIM / 128, NTOK / 128, EEXP), 256>>>(x, W1, b1);
    gemm2_kernel<<<dim3(DDIM / 128, NTOK / 128, EEXP), 256>>>(W2, b2);
    combine_kernel<<<(NTOK * DDIM / 4) / 256, 256>>>(out);
}

// round 3
// speedup vs baseline: 2.1819x; 2.1819x over previous
#include <cuda_runtime.h>
#include <cuda_bf16.h>
#include <math.h>
#include <stdint.h>

#define NTOK 32768
#define DDIM 256
#define EEXP 8
#define HDIM 1024
#define MAXENT (NTOK * 2)

// ---------------- static device scratch (no allocations) ----------------
__device__ __nv_bfloat16 g_xhi[(size_t)NTOK * DDIM];
__device__ __nv_bfloat16 g_xlo[(size_t)NTOK * DDIM];
__device__ __nv_bfloat16 g_hhi[(size_t)MAXENT * HDIM];
__device__ __nv_bfloat16 g_hlo[(size_t)MAXENT * HDIM];
__device__ __nv_bfloat16 g_w1t_hi[(size_t)EEXP * HDIM * DDIM];  // [E][H][D] K-major
__device__ __nv_bfloat16 g_w1t_lo[(size_t)EEXP * HDIM * DDIM];
__device__ __nv_bfloat16 g_w2t_hi[(size_t)EEXP * DDIM * HDIM];  // [E][D][H] K-major
__device__ __nv_bfloat16 g_w2t_lo[(size_t)EEXP * DDIM * HDIM];
__device__ int   g_idx[EEXP * NTOK];
__device__ float g_w  [EEXP * NTOK];
__device__ int   g_cnt[EEXP];
__device__ int   g_off[EEXP];

// ---------------- helpers ----------------
__device__ __forceinline__ uint32_t smem_u32(const void* p) {
    uint32_t a;
    asm("{ .reg .u64 t; cvta.to.shared.u64 t, %1; cvt.u32.u64 %0, t; }" : "=r"(a) : "l"(p));
    return a;
}
// conflict-free swizzle for 64B rows grouped as 128B units
__device__ __forceinline__ uint32_t swzl(uint32_t o) {
    return o ^ (((o >> 7) & 7) << 4);
}
__device__ __forceinline__ void cpa(uint32_t d, const void* s, int sz) {
    asm volatile("cp.async.cg.shared.global [%0], [%1], 16, %2;" :: "r"(d), "l"(s), "r"(sz));
}
__device__ __forceinline__ void cpa_commit() {
    asm volatile("cp.async.commit_group;" ::: "memory");
}
__device__ __forceinline__ void cpa_wait0() {
    asm volatile("cp.async.wait_group 0;" ::: "memory");
}
__device__ __forceinline__ void ldsm4(uint32_t* r, uint32_t a) {
    asm volatile("ldmatrix.sync.aligned.m8n8.x4.shared.b16 {%0,%1,%2,%3}, [%4];"
                 : "=r"(r[0]), "=r"(r[1]), "=r"(r[2]), "=r"(r[3]) : "r"(a));
}
__device__ __forceinline__ void mma16816(float* d, const uint32_t* a, uint32_t b0, uint32_t b1) {
    asm volatile("mma.sync.aligned.m16n8k16.row.col.f32.bf16.bf16.f32 "
                 "{%0,%1,%2,%3}, {%4,%5,%6,%7}, {%8,%9}, {%0,%1,%2,%3};"
                 : "+f"(d[0]), "+f"(d[1]), "+f"(d[2]), "+f"(d[3])
                 : "r"(a[0]), "r"(a[1]), "r"(a[2]), "r"(a[3]), "r"(b0), "r"(b1));
}
__device__ __forceinline__ float gelu_exact(float v) {
    return 0.5f * v * (1.0f + erff(v * 0.70710678118654752440f));
}

// ---------------- small kernels ----------------
__global__ void zero_cnt_kernel() {
    if (threadIdx.x < EEXP) g_cnt[threadIdx.x] = 0;
}
__global__ void zero_out_kernel(float* __restrict__ out) {
    const size_t i = (size_t)blockIdx.x * blockDim.x + threadIdx.x;
    ((float4*)out)[i] = make_float4(0.f, 0.f, 0.f, 0.f);
}
__global__ void prep_x_kernel(const float* __restrict__ x) {
    const size_t i = (size_t)blockIdx.x * 256 + threadIdx.x;
    const float v = x[i];
    const __nv_bfloat16 h = __float2bfloat16(v);
    g_xhi[i] = h;
    g_xlo[i] = __float2bfloat16(v - __bfloat162float(h));
}
// W: [E][R][C] fp32 -> T(hi/lo): [E][C][R] bf16
__global__ void prep_w_kernel(const float* __restrict__ W, int which, int R, int C) {
    __shared__ float t[32][33];
    const int e = blockIdx.z;
    const int c0 = blockIdx.x * 32, r0 = blockIdx.y * 32;
    const int tx = threadIdx.x, ty = threadIdx.y;
    t[ty][tx] = W[((size_t)e * R + r0 + ty) * C + c0 + tx];
    __syncthreads();
    const float v = t[tx][ty];
    const size_t oi = ((size_t)e * C + (c0 + ty)) * R + (r0 + tx);
    const __nv_bfloat16 h = __float2bfloat16(v);
    const __nv_bfloat16 l = __float2bfloat16(v - __bfloat162float(h));
    if (which == 0) { g_w1t_hi[oi] = h; g_w1t_lo[oi] = l; }
    else            { g_w2t_hi[oi] = h; g_w2t_lo[oi] = l; }
}

// ---------------- router (warp per token) ----------------
__global__ void router_kernel(const float* __restrict__ x,
                              const float* __restrict__ grad,
                              const float* __restrict__ Wr,
                              const float* __restrict__ br,
                              float* __restrict__ probs_out) {
    __shared__ float sWr[(DDIM + 1) * EEXP];
    __shared__ float sbr[EEXP];
    const int tid = threadIdx.x;
    for (int i = tid; i < (DDIM + 1) * EEXP; i += blockDim.x) sWr[i] = Wr[i];
    if (tid < EEXP) sbr[tid] = br[tid];
    __syncthreads();

    const int warp = tid >> 5, lane = tid & 31;
    const int n = blockIdx.x * 8 + warp;

    float acc[EEXP];
#pragma unroll
    for (int e = 0; e < EEXP; e++) acc[e] = 0.f;

    const float* xr = x + (size_t)n * DDIM;
#pragma unroll
    for (int it = 0; it < DDIM / 32; it++) {
        const int d = it * 32 + lane;
        const float xv = xr[d];
#pragma unroll
        for (int e = 0; e < EEXP; e++) acc[e] += xv * sWr[d * EEXP + e];
    }
#pragma unroll
    for (int e = 0; e < EEXP; e++) {
        float v = acc[e];
#pragma unroll
        for (int o = 16; o > 0; o >>= 1) v += __shfl_xor_sync(0xffffffffu, v, o);
        acc[e] = v;
    }
    if (lane == 0) {
        const float g = grad[n];
        float mx = -1e30f;
#pragma unroll
        for (int e = 0; e < EEXP; e++) {
            acc[e] += g * sWr[DDIM * EEXP + e] + sbr[e];
            mx = fmaxf(mx, acc[e]);
        }
        float s = 0.f;
#pragma unroll
        for (int e = 0; e < EEXP; e++) { acc[e] = expf(acc[e] - mx); s += acc[e]; }
        const float inv = 1.f / s;
#pragma unroll
        for (int e = 0; e < EEXP; e++) {
            acc[e] *= inv;
            probs_out[(size_t)n * EEXP + e] = acc[e];
        }
        int e0 = 0;
#pragma unroll
        for (int e = 1; e < EEXP; e++) if (acc[e] > acc[e0]) e0 = e;
        int e1 = (e0 == 0) ? 1 : 0;
#pragma unroll
        for (int e = 0; e < EEXP; e++) if (e != e0 && acc[e] > acc[e1]) e1 = e;

        int p0 = atomicAdd(&g_cnt[e0], 1);
        g_idx[e0 * NTOK + p0] = (n << 1);
        g_w  [e0 * NTOK + p0] = acc[e0];
        int p1 = atomicAdd(&g_cnt[e1], 1);
        g_idx[e1 * NTOK + p1] = (n << 1) | 1;
        g_w  [e1 * NTOK + p1] = acc[e1];
    }
}

__global__ void offsets_kernel() {
    if (threadIdx.x == 0) {
        int s = 0;
        for (int e = 0; e < EEXP; e++) { g_off[e] = s; s += g_cnt[e]; }
    }
}

// ---------------- HMMA GEMM: 128x128 CTA tile, K-chunk 32, 3-term bf16 split ----------------
// Stage layout (32KB): Ahi[128][32] @0 | Alo @8K | Bhi[128][32] @16K | Blo @24K  (bf16)
// G1=true : A = gathered x (K=256), B = W1T, epilogue gelu -> g_h hi/lo
// G1=false: A = g_h (K=1024), B = W2T, epilogue w*(acc+b2) atomicAdd -> out
template<int KDIM, bool G1>
__global__ __launch_bounds__(256, 2)
void moe_gemm_kernel(const float* __restrict__ bias, float* __restrict__ outp) {
    constexpr int NC = KDIM / 32;
    constexpr int BROWS = G1 ? HDIM : DDIM;

    const int e = blockIdx.z;
    const int cnt = g_cnt[e];
    const int m0 = blockIdx.y * 128;
    if (m0 >= cnt) return;
    const int n0 = blockIdx.x * 128;
    const int off = g_off[e];
    const int mRem = min(cnt - m0, 128);

    extern __shared__ char smem[];
    const uint32_t sb = smem_u32(smem);
    __shared__ float sBias[128];

    const int tid = threadIdx.x, lane = tid & 31, wid = tid >> 5;
    const int warpM = wid & 3, warpN = wid >> 2;   // 4 x 2 warp grid

    if (tid < 128) sBias[tid] = bias[e * BROWS + n0 + tid];

    // ---- global pointers for the loader (row r = tid>>1, half = tid&1) ----
    const int lr = tid >> 1, lh = tid & 1;
    const bool aval = lr < mRem;
    const __nv_bfloat16 *arow_h, *arow_l;
    {
        int row;
        if (G1) row = aval ? (g_idx[e * NTOK + m0 + lr] >> 1) : 0;
        else    row = aval ? (off + m0 + lr) : 0;
        if (G1) { arow_h = g_xhi + (size_t)row * KDIM; arow_l = g_xlo + (size_t)row * KDIM; }
        else    { arow_h = g_hhi + (size_t)row * KDIM; arow_l = g_hlo + (size_t)row * KDIM; }
    }
    const __nv_bfloat16* bt_h = (G1 ? g_w1t_hi : g_w2t_hi) + ((size_t)e * BROWS + n0 + lr) * KDIM;
    const __nv_bfloat16* bt_l = (G1 ? g_w1t_lo : g_w2t_lo) + ((size_t)e * BROWS + n0 + lr) * KDIM;

    const uint32_t st0 = swzl((uint32_t)lr * 64 + lh * 32);
    const uint32_t st1 = swzl((uint32_t)lr * 64 + lh * 32 + 16);
    const int asz = aval ? 16 : 0;

    // ---- ldmatrix fragment offsets (within stage) ----
    uint32_t aoff[2][2], boff[2][4];
#pragma unroll
    for (int ks = 0; ks < 2; ks++) {
#pragma unroll
        for (int mt = 0; mt < 2; mt++) {
            const uint32_t row = warpM * 32 + mt * 16 + (lane & 15);
            aoff[ks][mt] = swzl(row * 64 + ks * 32 + (lane >> 4) * 16);
        }
#pragma unroll
        for (int bt = 0; bt < 4; bt++) {
            const uint32_t row = warpN * 64 + bt * 16 + (lane & 7) + ((lane >> 4) & 1) * 8;
            boff[ks][bt] = 16384u + swzl(row * 64 + ks * 32 + ((lane >> 3) & 1) * 16);
        }
    }

    float acc[2][8][4];
#pragma unroll
    for (int i = 0; i < 2; i++)
#pragma unroll
        for (int j = 0; j < 8; j++)
#pragma unroll
            for (int q = 0; q < 4; q++) acc[i][j][q] = 0.f;

    auto load_chunk = [&](int kc, int stage) {
        const uint32_t s = sb + (uint32_t)stage * 32768u;
        const int go = kc * 32 + lh * 16;
        cpa(s + st0,          arow_h + go,     asz);
        cpa(s + st1,          arow_h + go + 8, asz);
        cpa(s + 8192 + st0,   arow_l + go,     asz);
        cpa(s + 8192 + st1,   arow_l + go + 8, asz);
        cpa(s + 16384 + st0,  bt_h + go,       16);
        cpa(s + 16384 + st1,  bt_h + go + 8,   16);
        cpa(s + 24576 + st0,  bt_l + go,       16);
        cpa(s + 24576 + st1,  bt_l + go + 8,   16);
    };

    load_chunk(0, 0);
    cpa_commit();

    for (int c = 0; c < NC; c++) {
        cpa_wait0();
        __syncthreads();
        if (c + 1 < NC) { load_chunk(c + 1, (c + 1) & 1); cpa_commit(); }

        const uint32_t ss = sb + (uint32_t)(c & 1) * 32768u;
#pragma unroll
        for (int ks = 0; ks < 2; ks++) {
            uint32_t ah[2][4], al[2][4], bb[4][4];
            ldsm4(ah[0], ss + aoff[ks][0]);
            ldsm4(ah[1], ss + aoff[ks][1]);
            ldsm4(al[0], ss + 8192 + aoff[ks][0]);
            ldsm4(al[1], ss + 8192 + aoff[ks][1]);
#pragma unroll
            for (int bt = 0; bt < 4; bt++) ldsm4(bb[bt], ss + boff[ks][bt]);
#pragma unroll
            for (int mt = 0; mt < 2; mt++)
#pragma unroll
                for (int bt = 0; bt < 4; bt++) {
                    mma16816(acc[mt][2 * bt],     ah[mt], bb[bt][0], bb[bt][1]);
                    mma16816(acc[mt][2 * bt + 1], ah[mt], bb[bt][2], bb[bt][3]);
                    mma16816(acc[mt][2 * bt],     al[mt], bb[bt][0], bb[bt][1]);
                    mma16816(acc[mt][2 * bt + 1], al[mt], bb[bt][2], bb[bt][3]);
                }
            // reload B with lo-halves, third term Ah*Bl
#pragma unroll
            for (int bt = 0; bt < 4; bt++) ldsm4(bb[bt], ss + 8192 + boff[ks][bt]);
#pragma unroll
            for (int mt = 0; mt < 2; mt++)
#pragma unroll
                for (int bt = 0; bt < 4; bt++) {
                    mma16816(acc[mt][2 * bt],     ah[mt], bb[bt][0], bb[bt][1]);
                    mma16816(acc[mt][2 * bt + 1], ah[mt], bb[bt][2], bb[bt][3]);
                }
        }
        __syncthreads();
    }

    // ---------------- epilogue ----------------
    const int gid = lane >> 2, tig = lane & 3;
#pragma unroll
    for (int mt = 0; mt < 2; mt++) {
#pragma unroll
        for (int half = 0; half < 2; half++) {
            const int ml = warpM * 32 + mt * 16 + gid + half * 8;
            if (ml >= mRem) continue;
            if (G1) {
                const size_t ob = (size_t)(off + m0 + ml) * HDIM + n0;
#pragma unroll
                for (int nt = 0; nt < 8; nt++) {
                    const int col = warpN * 64 + nt * 8 + tig * 2;
                    float v0 = gelu_exact(acc[mt][nt][half * 2]     + sBias[col]);
                    float v1 = gelu_exact(acc[mt][nt][half * 2 + 1] + sBias[col + 1]);
                    __nv_bfloat16 h0 = __float2bfloat16(v0);
                    __nv_bfloat16 h1 = __float2bfloat16(v1);
                    __nv_bfloat162 hp; hp.x = h0; hp.y = h1;
                    __nv_bfloat162 lp;
                    lp.x = __float2bfloat16(v0 - __bfloat162float(h0));
                    lp.y = __float2bfloat16(v1 - __bfloat162float(h1));
                    *(uint32_t*)(g_hhi + ob + col) = *(uint32_t*)&hp;
                    *(uint32_t*)(g_hlo + ob + col) = *(uint32_t*)&lp;
                }
            } else {
                const int ent = g_idx[e * NTOK + m0 + ml];
                const float wgt = g_w[e * NTOK + m0 + ml];
                float* dst = outp + (size_t)(ent >> 1) * DDIM + n0;
#pragma unroll
                for (int nt = 0; nt < 8; nt++) {
                    const int col = warpN * 64 + nt * 8 + tig * 2;
                    atomicAdd(dst + col,     wgt * (acc[mt][nt][half * 2]     + sBias[col]));
                    atomicAdd(dst + col + 1, wgt * (acc[mt][nt][half * 2 + 1] + sBias[col + 1]));
                }
            }
        }
    }
}

// ---------------- launch ----------------
extern "C" void kernel_launch(void* const* d_in, const int* in_sizes, int n_in,
                              void* d_out, int out_size) {
    const float* x    = (const float*)d_in[0];
    const float* grad = (const float*)d_in[1];
    const float* Wr   = (const float*)d_in[2];
    const float* br   = (const float*)d_in[3];
    const float* W1   = (const float*)d_in[4];
    const float* b1   = (const float*)d_in[5];
    const float* W2   = (const float*)d_in[6];
    const float* b2   = (const float*)d_in[7];
    float* out   = (float*)d_out;
    float* probs = out + (size_t)NTOK * DDIM;

    const int SMEM_DYN = 65536;
    cudaFuncSetAttribute(moe_gemm_kernel<DDIM, true>,  cudaFuncAttributeMaxDynamicSharedMemorySize, SMEM_DYN);
    cudaFuncSetAttribute(moe_gemm_kernel<HDIM, false>, cudaFuncAttributeMaxDynamicSharedMemorySize, SMEM_DYN);

    zero_cnt_kernel<<<1, 32>>>();
    zero_out_kernel<<<(NTOK * DDIM / 4) / 256, 256>>>(out);
    prep_x_kernel<<<NTOK * DDIM / 256, 256>>>(x);
    prep_w_kernel<<<dim3(HDIM / 32, DDIM / 32, EEXP), dim3(32, 32)>>>(W1, 0, DDIM, HDIM);
    prep_w_kernel<<<dim3(DDIM / 32, HDIM / 32, EEXP), dim3(32, 32)>>>(W2, 1, HDIM, DDIM);
    router_kernel<<<NTOK / 8, 256>>>(x, grad, Wr, br, probs);
    offsets_kernel<<<1, 32>>>();
    moe_gemm_kernel<DDIM, true><<<dim3(HDIM / 128, NTOK / 128, EEXP), 256, SMEM_DYN>>>(b1, nullptr);
    moe_gemm_kernel<HDIM, false><<<dim3(DDIM / 128, NTOK / 128, EEXP), 256, SMEM_DYN>>>(b2, out);
}

// round 4
// speedup vs baseline: 2.9530x; 1.3534x over previous
#include <cuda_runtime.h>
#include <cuda_fp16.h>
#include <math.h>
#include <stdint.h>

#define NTOK 32768
#define DDIM 256
#define EEXP 8
#define HDIM 1024
#define MAXENT (NTOK * 2)

// ---------------- static device scratch (no allocations) ----------------
__device__ __half g_xh[(size_t)NTOK * DDIM];
__device__ __half g_xl[(size_t)NTOK * DDIM];
__device__ __half g_hh[(size_t)MAXENT * HDIM];
__device__ __half g_hl[(size_t)MAXENT * HDIM];
__device__ __half g_w1t[(size_t)EEXP * HDIM * DDIM];  // [E][H][D] K-major, fp16
__device__ __half g_w2t[(size_t)EEXP * DDIM * HDIM];  // [E][D][H] K-major, fp16
__device__ int   g_idx[EEXP * NTOK];
__device__ float g_w  [EEXP * NTOK];
__device__ int   g_cnt[EEXP];
__device__ int   g_off[EEXP];

// ---------------- helpers ----------------
__device__ __forceinline__ uint32_t smem_u32(const void* p) {
    uint32_t a;
    asm("{ .reg .u64 t; cvta.to.shared.u64 t, %1; cvt.u32.u64 %0, t; }" : "=r"(a) : "l"(p));
    return a;
}
__device__ __forceinline__ uint32_t swzl(uint32_t o) {
    return o ^ (((o >> 7) & 7) << 4);
}
__device__ __forceinline__ void cpa(uint32_t d, const void* s, int sz) {
    asm volatile("cp.async.cg.shared.global [%0], [%1], 16, %2;" :: "r"(d), "l"(s), "r"(sz));
}
__device__ __forceinline__ void cpa_commit() {
    asm volatile("cp.async.commit_group;" ::: "memory");
}
__device__ __forceinline__ void cpa_wait0() {
    asm volatile("cp.async.wait_group 0;" ::: "memory");
}
__device__ __forceinline__ void cpa_wait1() {
    asm volatile("cp.async.wait_group 1;" ::: "memory");
}
__device__ __forceinline__ void ldsm4(uint32_t* r, uint32_t a) {
    asm volatile("ldmatrix.sync.aligned.m8n8.x4.shared.b16 {%0,%1,%2,%3}, [%4];"
                 : "=r"(r[0]), "=r"(r[1]), "=r"(r[2]), "=r"(r[3]) : "r"(a));
}
__device__ __forceinline__ void mma16816(float* d, const uint32_t* a, uint32_t b0, uint32_t b1) {
    asm volatile("mma.sync.aligned.m16n8k16.row.col.f32.f16.f16.f32 "
                 "{%0,%1,%2,%3}, {%4,%5,%6,%7}, {%8,%9}, {%0,%1,%2,%3};"
                 : "+f"(d[0]), "+f"(d[1]), "+f"(d[2]), "+f"(d[3])
                 : "r"(a[0]), "r"(a[1]), "r"(a[2]), "r"(a[3]), "r"(b0), "r"(b1));
}
__device__ __forceinline__ float gelu_exact(float v) {
    return 0.5f * v * (1.0f + erff(v * 0.70710678118654752440f));
}

// ---------------- small kernels ----------------
__global__ void zero_out_kernel(float* __restrict__ out) {
    const size_t i = (size_t)blockIdx.x * blockDim.x + threadIdx.x;
    ((float4*)out)[i] = make_float4(0.f, 0.f, 0.f, 0.f);
}
__global__ void prep_x_kernel(const float* __restrict__ x) {
    if (blockIdx.x == 0 && threadIdx.x < EEXP) g_cnt[threadIdx.x] = 0;
    const size_t i = (size_t)blockIdx.x * 256 + threadIdx.x;
    const float v = x[i];
    const __half h = __float2half(v);
    g_xh[i] = h;
    g_xl[i] = __float2half(v - __half2float(h));
}
// W: [E][R][C] fp32 -> T: [E][C][R] fp16
__global__ void prep_w_kernel(const float* __restrict__ W, int which, int R, int C) {
    __shared__ float t[32][33];
    const int e = blockIdx.z;
    const int c0 = blockIdx.x * 32, r0 = blockIdx.y * 32;
    const int tx = threadIdx.x, ty = threadIdx.y;
    t[ty][tx] = W[((size_t)e * R + r0 + ty) * C + c0 + tx];
    __syncthreads();
    const float v = t[tx][ty];
    const size_t oi = ((size_t)e * C + (c0 + ty)) * R + (r0 + tx);
    if (which == 0) g_w1t[oi] = __float2half(v);
    else            g_w2t[oi] = __float2half(v);
}

// ---------------- router (warp per token) ----------------
__global__ void router_kernel(const float* __restrict__ x,
                              const float* __restrict__ grad,
                              const float* __restrict__ Wr,
                              const float* __restrict__ br,
                              float* __restrict__ probs_out) {
    __shared__ float sWr[(DDIM + 1) * EEXP];
    __shared__ float sbr[EEXP];
    const int tid = threadIdx.x;
    for (int i = tid; i < (DDIM + 1) * EEXP; i += blockDim.x) sWr[i] = Wr[i];
    if (tid < EEXP) sbr[tid] = br[tid];
    __syncthreads();

    const int warp = tid >> 5, lane = tid & 31;
    const int n = blockIdx.x * 8 + warp;

    float acc[EEXP];
#pragma unroll
    for (int e = 0; e < EEXP; e++) acc[e] = 0.f;

    const float* xr = x + (size_t)n * DDIM;
#pragma unroll
    for (int it = 0; it < DDIM / 32; it++) {
        const int d = it * 32 + lane;
        const float xv = xr[d];
#pragma unroll
        for (int e = 0; e < EEXP; e++) acc[e] += xv * sWr[d * EEXP + e];
    }
#pragma unroll
    for (int e = 0; e < EEXP; e++) {
        float v = acc[e];
#pragma unroll
        for (int o = 16; o > 0; o >>= 1) v += __shfl_xor_sync(0xffffffffu, v, o);
        acc[e] = v;
    }
    if (lane == 0) {
        const float g = grad[n];
        float mx = -1e30f;
#pragma unroll
        for (int e = 0; e < EEXP; e++) {
            acc[e] += g * sWr[DDIM * EEXP + e] + sbr[e];
            mx = fmaxf(mx, acc[e]);
        }
        float s = 0.f;
#pragma unroll
        for (int e = 0; e < EEXP; e++) { acc[e] = expf(acc[e] - mx); s += acc[e]; }
        const float inv = 1.f / s;
#pragma unroll
        for (int e = 0; e < EEXP; e++) {
            acc[e] *= inv;
            probs_out[(size_t)n * EEXP + e] = acc[e];
        }
        int e0 = 0;
#pragma unroll
        for (int e = 1; e < EEXP; e++) if (acc[e] > acc[e0]) e0 = e;
        int e1 = (e0 == 0) ? 1 : 0;
#pragma unroll
        for (int e = 0; e < EEXP; e++) if (e != e0 && acc[e] > acc[e1]) e1 = e;

        int p0 = atomicAdd(&g_cnt[e0], 1);
        g_idx[e0 * NTOK + p0] = (n << 1);
        g_w  [e0 * NTOK + p0] = acc[e0];
        int p1 = atomicAdd(&g_cnt[e1], 1);
        g_idx[e1 * NTOK + p1] = (n << 1) | 1;
        g_w  [e1 * NTOK + p1] = acc[e1];
    }
}

__global__ void offsets_kernel() {
    if (threadIdx.x == 0) {
        int s = 0;
        for (int e = 0; e < EEXP; e++) { g_off[e] = s; s += g_cnt[e]; }
    }
}

// ---------------- HMMA GEMM: 128x128 CTA tile, K-chunk 32, 2-term fp16 split ----------------
// Stage (24KB): Ah[128][32] @0 | Al @8K | B[128][32] @16K   (fp16)
// G1=true : A = gathered x (K=256), B = W1T, epilogue gelu -> g_h hi/lo
// G1=false: A = g_h (K=1024), B = W2T, epilogue w*(acc+b2) atomicAdd -> out
template<int KDIM, bool G1>
__global__ __launch_bounds__(256, 2)
void moe_gemm_kernel(const float* __restrict__ bias, float* __restrict__ outp) {
    constexpr int NC = KDIM / 32;
    constexpr int BROWS = G1 ? HDIM : DDIM;
    constexpr uint32_t STAGE = 24576;

    const int e = blockIdx.z;
    const int cnt = g_cnt[e];
    const int m0 = blockIdx.y * 128;
    if (m0 >= cnt) return;
    const int n0 = blockIdx.x * 128;
    const int off = g_off[e];
    const int mRem = min(cnt - m0, 128);

    extern __shared__ char smem[];
    const uint32_t sb = smem_u32(smem);
    __shared__ float sBias[128];

    const int tid = threadIdx.x, lane = tid & 31, wid = tid >> 5;
    const int warpM = wid & 3, warpN = wid >> 2;   // 4 x 2 warp grid, warp tile 32x64

    if (tid < 128) sBias[tid] = bias[e * BROWS + n0 + tid];

    // ---- loader: row lr = tid>>1, half lh = tid&1 (32B each) ----
    const int lr = tid >> 1, lh = tid & 1;
    const bool aval = lr < mRem;
    const __half *arow_h, *arow_l;
    {
        int row;
        if (G1) row = aval ? (g_idx[e * NTOK + m0 + lr] >> 1) : 0;
        else    row = aval ? (off + m0 + lr) : 0;
        if (G1) { arow_h = g_xh + (size_t)row * KDIM; arow_l = g_xl + (size_t)row * KDIM; }
        else    { arow_h = g_hh + (size_t)row * KDIM; arow_l = g_hl + (size_t)row * KDIM; }
    }
    const __half* bt = (G1 ? g_w1t : g_w2t) + ((size_t)e * BROWS + n0 + lr) * KDIM;

    const uint32_t st0 = swzl((uint32_t)lr * 64 + lh * 32);
    const uint32_t st1 = swzl((uint32_t)lr * 64 + lh * 32 + 16);
    const int asz = aval ? 16 : 0;

    // ---- ldmatrix fragment offsets (within stage) ----
    uint32_t aoff[2][2], boff[2][4];
#pragma unroll
    for (int ks = 0; ks < 2; ks++) {
#pragma unroll
        for (int mt = 0; mt < 2; mt++) {
            const uint32_t row = warpM * 32 + mt * 16 + (lane & 15);
            aoff[ks][mt] = swzl(row * 64 + ks * 32 + (lane >> 4) * 16);
        }
#pragma unroll
        for (int btj = 0; btj < 4; btj++) {
            const uint32_t row = warpN * 64 + btj * 16 + (lane & 7) + ((lane >> 4) & 1) * 8;
            boff[ks][btj] = 16384u + swzl(row * 64 + ks * 32 + ((lane >> 3) & 1) * 16);
        }
    }

    float acc[2][8][4];
#pragma unroll
    for (int i = 0; i < 2; i++)
#pragma unroll
        for (int j = 0; j < 8; j++)
#pragma unroll
            for (int q = 0; q < 4; q++) acc[i][j][q] = 0.f;

    auto load_chunk = [&](int kc, int stage) {
        const uint32_t s = sb + (uint32_t)stage * STAGE;
        const int go = kc * 32 + lh * 16;
        cpa(s + st0,         arow_h + go,     asz);
        cpa(s + st1,         arow_h + go + 8, asz);
        cpa(s + 8192 + st0,  arow_l + go,     asz);
        cpa(s + 8192 + st1,  arow_l + go + 8, asz);
        cpa(s + 16384 + st0, bt + go,         16);
        cpa(s + 16384 + st1, bt + go + 8,     16);
    };

    load_chunk(0, 0);
    cpa_commit();

    for (int c = 0; c < NC; c++) {
        if (c + 1 < NC) {
            load_chunk(c + 1, (c + 1) & 1);
            cpa_commit();
            cpa_wait1();            // chunk c complete, c+1 still in flight
        } else {
            cpa_wait0();
        }
        __syncthreads();

        const uint32_t ss = sb + (uint32_t)(c & 1) * STAGE;
#pragma unroll
        for (int ks = 0; ks < 2; ks++) {
            uint32_t ah[2][4], al[2][4], bb[4][4];
            ldsm4(ah[0], ss + aoff[ks][0]);
            ldsm4(ah[1], ss + aoff[ks][1]);
            ldsm4(al[0], ss + 8192 + aoff[ks][0]);
            ldsm4(al[1], ss + 8192 + aoff[ks][1]);
#pragma unroll
            for (int btj = 0; btj < 4; btj++) ldsm4(bb[btj], ss + boff[ks][btj]);
#pragma unroll
            for (int mt = 0; mt < 2; mt++)
#pragma unroll
                for (int btj = 0; btj < 4; btj++) {
                    mma16816(acc[mt][2 * btj],     ah[mt], bb[btj][0], bb[btj][1]);
                    mma16816(acc[mt][2 * btj + 1], ah[mt], bb[btj][2], bb[btj][3]);
                    mma16816(acc[mt][2 * btj],     al[mt], bb[btj][0], bb[btj][1]);
                    mma16816(acc[mt][2 * btj + 1], al[mt], bb[btj][2], bb[btj][3]);
                }
        }
        __syncthreads();
    }

    // ---------------- epilogue ----------------
    const int gid = lane >> 2, tig = lane & 3;
#pragma unroll
    for (int mt = 0; mt < 2; mt++) {
#pragma unroll
        for (int half = 0; half < 2; half++) {
            const int ml = warpM * 32 + mt * 16 + gid + half * 8;
            if (ml >= mRem) continue;
            if (G1) {
                const size_t ob = (size_t)(off + m0 + ml) * HDIM + n0;
#pragma unroll
                for (int nt = 0; nt < 8; nt++) {
                    const int col = warpN * 64 + nt * 8 + tig * 2;
                    float v0 = gelu_exact(acc[mt][nt][half * 2]     + sBias[col]);
                    float v1 = gelu_exact(acc[mt][nt][half * 2 + 1] + sBias[col + 1]);
                    __half h0 = __float2half(v0);
                    __half h1 = __float2half(v1);
                    __half2 hp; hp.x = h0; hp.y = h1;
                    __half2 lp;
                    lp.x = __float2half(v0 - __half2float(h0));
                    lp.y = __float2half(v1 - __half2float(h1));
                    *(uint32_t*)(g_hh + ob + col) = *(uint32_t*)&hp;
                    *(uint32_t*)(g_hl + ob + col) = *(uint32_t*)&lp;
                }
            } else {
                const int ent = g_idx[e * NTOK + m0 + ml];
                const float wgt = g_w[e * NTOK + m0 + ml];
                float* dst = outp + (size_t)(ent >> 1) * DDIM + n0;
#pragma unroll
                for (int nt = 0; nt < 8; nt++) {
                    const int col = warpN * 64 + nt * 8 + tig * 2;
                    atomicAdd(dst + col,     wgt * (acc[mt][nt][half * 2]     + sBias[col]));
                    atomicAdd(dst + col + 1, wgt * (acc[mt][nt][half * 2 + 1] + sBias[col + 1]));
                }
            }
        }
    }
}

// ---------------- launch ----------------
extern "C" void kernel_launch(void* const* d_in, const int* in_sizes, int n_in,
                              void* d_out, int out_size) {
    const float* x    = (const float*)d_in[0];
    const float* grad = (const float*)d_in[1];
    const float* Wr   = (const float*)d_in[2];
    const float* br   = (const float*)d_in[3];
    const float* W1   = (const float*)d_in[4];
    const float* b1   = (const float*)d_in[5];
    const float* W2   = (const float*)d_in[6];
    const float* b2   = (const float*)d_in[7];
    float* out   = (float*)d_out;
    float* probs = out + (size_t)NTOK * DDIM;

    const int SMEM_DYN = 49152;
    cudaFuncSetAttribute(moe_gemm_kernel<DDIM, true>,  cudaFuncAttributeMaxDynamicSharedMemorySize, SMEM_DYN);
    cudaFuncSetAttribute(moe_gemm_kernel<HDIM, false>, cudaFuncAttributeMaxDynamicSharedMemorySize, SMEM_DYN);

    // launch order chosen so gemm1 is launch #6 (ncu -s 5 -c 1 captures it)
    prep_x_kernel<<<NTOK * DDIM / 256, 256>>>(x);                                    // 1 (also zeroes g_cnt)
    prep_w_kernel<<<dim3(HDIM / 32, DDIM / 32, EEXP), dim3(32, 32)>>>(W1, 0, DDIM, HDIM); // 2
    prep_w_kernel<<<dim3(DDIM / 32, HDIM / 32, EEXP), dim3(32, 32)>>>(W2, 1, HDIM, DDIM); // 3
    router_kernel<<<NTOK / 8, 256>>>(x, grad, Wr, br, probs);                        // 4
    offsets_kernel<<<1, 32>>>();                                                     // 5
    moe_gemm_kernel<DDIM, true><<<dim3(HDIM / 128, NTOK / 128, EEXP), 256, SMEM_DYN>>>(b1, nullptr); // 6
    zero_out_kernel<<<(NTOK * DDIM / 4) / 256, 256>>>(out);                          // 7
    moe_gemm_kernel<HDIM, false><<<dim3(DDIM / 128, NTOK / 128, EEXP), 256, SMEM_DYN>>>(b2, out);    // 8
}

// round 5
// speedup vs baseline: 4.2563x; 1.4414x over previous
#include <cuda_runtime.h>
#include <cuda_fp16.h>
#include <math.h>
#include <stdint.h>

#define NTOK 32768
#define DDIM 256
#define EEXP 8
#define HDIM 1024
#define MAXENT (NTOK * 2)

// ---------------- static device scratch (no allocations) ----------------
__device__ __half g_xh[(size_t)NTOK * DDIM];
__device__ __half g_hh[(size_t)MAXENT * HDIM];
__device__ __half g_w1t[(size_t)EEXP * HDIM * DDIM];  // [E][H][D] K-major fp16
__device__ __half g_w2t[(size_t)EEXP * DDIM * HDIM];  // [E][D][H] K-major fp16
__device__ int   g_idx[EEXP * NTOK];
__device__ float g_w  [EEXP * NTOK];
__device__ int   g_cnt[EEXP];

// ---------------- helpers ----------------
__device__ __forceinline__ uint32_t smem_u32(const void* p) {
    uint32_t a;
    asm("{ .reg .u64 t; cvta.to.shared.u64 t, %1; cvt.u32.u64 %0, t; }" : "=r"(a) : "l"(p));
    return a;
}
__device__ __forceinline__ uint32_t swzl(uint32_t o) {
    return o ^ (((o >> 7) & 7) << 4);
}
__device__ __forceinline__ void cpa(uint32_t d, const void* s, int sz) {
    asm volatile("cp.async.cg.shared.global [%0], [%1], 16, %2;" :: "r"(d), "l"(s), "r"(sz));
}
__device__ __forceinline__ void cpa_commit() {
    asm volatile("cp.async.commit_group;" ::: "memory");
}
template<int N>
__device__ __forceinline__ void cpa_wait() {
    asm volatile("cp.async.wait_group %0;" :: "n"(N) : "memory");
}
__device__ __forceinline__ void ldsm4(uint32_t* r, uint32_t a) {
    asm volatile("ldmatrix.sync.aligned.m8n8.x4.shared.b16 {%0,%1,%2,%3}, [%4];"
                 : "=r"(r[0]), "=r"(r[1]), "=r"(r[2]), "=r"(r[3]) : "r"(a));
}
__device__ __forceinline__ void mma16816(float* d, const uint32_t* a, uint32_t b0, uint32_t b1) {
    asm volatile("mma.sync.aligned.m16n8k16.row.col.f32.f16.f16.f32 "
                 "{%0,%1,%2,%3}, {%4,%5,%6,%7}, {%8,%9}, {%0,%1,%2,%3};"
                 : "+f"(d[0]), "+f"(d[1]), "+f"(d[2]), "+f"(d[3])
                 : "r"(a[0]), "r"(a[1]), "r"(a[2]), "r"(a[3]), "r"(b0), "r"(b1));
}
__device__ __forceinline__ float gelu_exact(float v) {
    return 0.5f * v * (1.0f + erff(v * 0.70710678118654752440f));
}

// ---------------- launch 1: zero out + counters ----------------
__global__ void zero_out_kernel(float* __restrict__ out) {
    if (blockIdx.x == 0 && threadIdx.x < EEXP) g_cnt[threadIdx.x] = 0;
    const size_t i = (size_t)blockIdx.x * blockDim.x + threadIdx.x;
    ((float4*)out)[i] = make_float4(0.f, 0.f, 0.f, 0.f);
}

// ---------------- launch 2: weight transpose+convert, W1 and W2 in one grid ----------------
// grid (32, 8, 16): z<8 -> W1[e=z]: R=256,C=1024, c0=bx*32, r0=by*32
//                   z>=8 -> W2[e=z-8]: R=1024,C=256, c0=by*32, r0=bx*32
__global__ void prep_w_kernel(const float* __restrict__ W1, const float* __restrict__ W2) {
    __shared__ float t[32][33];
    const int z = blockIdx.z;
    const bool isW1 = z < EEXP;
    const int e = isW1 ? z : z - EEXP;
    const int R = isW1 ? DDIM : HDIM;
    const int C = isW1 ? HDIM : DDIM;
    const int c0 = (isW1 ? blockIdx.x : blockIdx.y) * 32;
    const int r0 = (isW1 ? blockIdx.y : blockIdx.x) * 32;
    const float* W = isW1 ? W1 : W2;
    const int tx = threadIdx.x, ty = threadIdx.y;
    t[ty][tx] = W[((size_t)e * R + r0 + ty) * C + c0 + tx];
    __syncthreads();
    const float v = t[tx][ty];
    const size_t oi = ((size_t)e * C + (c0 + ty)) * R + (r0 + tx);
    if (isW1) g_w1t[oi] = __float2half(v);
    else      g_w2t[oi] = __float2half(v);
}

// ---------------- launch 3: router + x->fp16 (warp per token) ----------------
__global__ void router_kernel(const float* __restrict__ x,
                              const float* __restrict__ grad,
                              const float* __restrict__ Wr,
                              const float* __restrict__ br,
                              float* __restrict__ probs_out) {
    __shared__ float sWrT[EEXP][DDIM];   // transposed: conflict-free reads
    __shared__ float sWg[EEXP];          // grad-feature row
    __shared__ float sbr[EEXP];
    const int tid = threadIdx.x;
    for (int i = tid; i < DDIM * EEXP; i += blockDim.x) {
        const int d = i >> 3, e = i & 7;
        sWrT[e][d] = Wr[d * EEXP + e];
    }
    if (tid < EEXP) { sWg[tid] = Wr[DDIM * EEXP + tid]; sbr[tid] = br[tid]; }
    __syncthreads();

    const int warp = tid >> 5, lane = tid & 31;
    const int n = blockIdx.x * 8 + warp;

    float acc[EEXP];
#pragma unroll
    for (int e = 0; e < EEXP; e++) acc[e] = 0.f;

    const float* xr = x + (size_t)n * DDIM;
    __half* xh = g_xh + (size_t)n * DDIM;
#pragma unroll
    for (int it = 0; it < DDIM / 32; it++) {
        const int d = it * 32 + lane;
        const float xv = xr[d];
        xh[d] = __float2half(xv);
#pragma unroll
        for (int e = 0; e < EEXP; e++) acc[e] += xv * sWrT[e][d];
    }
#pragma unroll
    for (int e = 0; e < EEXP; e++) {
        float v = acc[e];
#pragma unroll
        for (int o = 16; o > 0; o >>= 1) v += __shfl_xor_sync(0xffffffffu, v, o);
        acc[e] = v;
    }
    if (lane == 0) {
        const float g = grad[n];
        float mx = -1e30f;
#pragma unroll
        for (int e = 0; e < EEXP; e++) {
            acc[e] += g * sWg[e] + sbr[e];
            mx = fmaxf(mx, acc[e]);
        }
        float s = 0.f;
#pragma unroll
        for (int e = 0; e < EEXP; e++) { acc[e] = expf(acc[e] - mx); s += acc[e]; }
        const float inv = 1.f / s;
#pragma unroll
        for (int e = 0; e < EEXP; e++) {
            acc[e] *= inv;
            probs_out[(size_t)n * EEXP + e] = acc[e];
        }
        int e0 = 0;
#pragma unroll
        for (int e = 1; e < EEXP; e++) if (acc[e] > acc[e0]) e0 = e;
        int e1 = (e0 == 0) ? 1 : 0;
#pragma unroll
        for (int e = 0; e < EEXP; e++) if (e != e0 && acc[e] > acc[e1]) e1 = e;

        int p0 = atomicAdd(&g_cnt[e0], 1);
        g_idx[e0 * NTOK + p0] = (n << 1);
        g_w  [e0 * NTOK + p0] = acc[e0];
        int p1 = atomicAdd(&g_cnt[e1], 1);
        g_idx[e1 * NTOK + p1] = (n << 1) | 1;
        g_w  [e1 * NTOK + p1] = acc[e1];
    }
}

// ---------------- launches 4/5: HMMA GEMM, 128x128 tile, K-chunk 32, fp16, 3-stage ----------------
// Stage (16KB): A[128][32] @0 | B[128][32] @8K
// G1=true : A = gathered x (K=256), B = W1T, epilogue gelu -> g_hh
// G1=false: A = g_hh (K=1024), B = W2T, epilogue w*(acc+b2) atomicAdd -> out
template<int KDIM, bool G1>
__global__ __launch_bounds__(256, 2)
void moe_gemm_kernel(const float* __restrict__ bias, float* __restrict__ outp) {
    constexpr int NC = KDIM / 32;
    constexpr int BROWS = G1 ? HDIM : DDIM;
    constexpr uint32_t STAGE = 16384;

    const int e = blockIdx.z;
    int off = 0;
#pragma unroll
    for (int i = 0; i < EEXP; i++) if (i < e) off += g_cnt[i];
    const int cnt = g_cnt[e];
    const int m0 = blockIdx.y * 128;
    if (m0 >= cnt) return;
    const int n0 = blockIdx.x * 128;
    const int mRem = min(cnt - m0, 128);

    extern __shared__ char smem[];
    const uint32_t sb = smem_u32(smem);
    __shared__ float sBias[128];

    const int tid = threadIdx.x, lane = tid & 31, wid = tid >> 5;
    const int warpM = wid & 3, warpN = wid >> 2;   // 4x2 warps, warp tile 32x64

    if (tid < 128) sBias[tid] = bias[e * BROWS + n0 + tid];

    // loader: row lr = tid>>1, half lh = tid&1 (32B each)
    const int lr = tid >> 1, lh = tid & 1;
    const bool aval = lr < mRem;
    const __half* arow;
    {
        int row;
        if (G1) row = aval ? (g_idx[e * NTOK + m0 + lr] >> 1) : 0;
        else    row = aval ? (off + m0 + lr) : 0;
        arow = (G1 ? g_xh : g_hh) + (size_t)row * KDIM;
    }
    const __half* bt = (G1 ? g_w1t : g_w2t) + ((size_t)e * BROWS + n0 + lr) * KDIM;

    const uint32_t st0 = swzl((uint32_t)lr * 64 + lh * 32);
    const uint32_t st1 = swzl((uint32_t)lr * 64 + lh * 32 + 16);
    const int asz = aval ? 16 : 0;

    uint32_t aoff[2][2], boff[2][4];
#pragma unroll
    for (int ks = 0; ks < 2; ks++) {
#pragma unroll
        for (int mt = 0; mt < 2; mt++) {
            const uint32_t row = warpM * 32 + mt * 16 + (lane & 15);
            aoff[ks][mt] = swzl(row * 64 + ks * 32 + (lane >> 4) * 16);
        }
#pragma unroll
        for (int btj = 0; btj < 4; btj++) {
            const uint32_t row = warpN * 64 + btj * 16 + (lane & 7) + ((lane >> 4) & 1) * 8;
            boff[ks][btj] = 8192u + swzl(row * 64 + ks * 32 + ((lane >> 3) & 1) * 16);
        }
    }

    float acc[2][8][4];
#pragma unroll
    for (int i = 0; i < 2; i++)
#pragma unroll
        for (int j = 0; j < 8; j++)
#pragma unroll
            for (int q = 0; q < 4; q++) acc[i][j][q] = 0.f;

    auto load_chunk = [&](int kc, int stage) {
        const uint32_t s = sb + (uint32_t)stage * STAGE;
        const int go = kc * 32 + lh * 16;
        cpa(s + st0,        arow + go,     asz);
        cpa(s + st1,        arow + go + 8, asz);
        cpa(s + 8192 + st0, bt + go,       16);
        cpa(s + 8192 + st1, bt + go + 8,   16);
    };

    load_chunk(0, 0);
    cpa_commit();
    load_chunk(1, 1);
    cpa_commit();

    int stage = 0;
    for (int c = 0; c < NC; c++) {
        if (c + 2 < NC) {
            int ps = stage + 2; if (ps >= 3) ps -= 3;
            load_chunk(c + 2, ps);
            cpa_commit();
            cpa_wait<2>();
        } else if (c + 1 < NC) {
            cpa_wait<1>();
        } else {
            cpa_wait<0>();
        }
        __syncthreads();

        const uint32_t ss = sb + (uint32_t)stage * STAGE;
#pragma unroll
        for (int ks = 0; ks < 2; ks++) {
            uint32_t ah[2][4], bb[4][4];
            ldsm4(ah[0], ss + aoff[ks][0]);
            ldsm4(ah[1], ss + aoff[ks][1]);
#pragma unroll
            for (int btj = 0; btj < 4; btj++) ldsm4(bb[btj], ss + boff[ks][btj]);
#pragma unroll
            for (int mt = 0; mt < 2; mt++)
#pragma unroll
                for (int btj = 0; btj < 4; btj++) {
                    mma16816(acc[mt][2 * btj],     ah[mt], bb[btj][0], bb[btj][1]);
                    mma16816(acc[mt][2 * btj + 1], ah[mt], bb[btj][2], bb[btj][3]);
                }
        }
        __syncthreads();
        if (++stage == 3) stage = 0;
    }

    // ---------------- epilogue ----------------
    const int gid = lane >> 2, tig = lane & 3;
#pragma unroll
    for (int mt = 0; mt < 2; mt++) {
#pragma unroll
        for (int half = 0; half < 2; half++) {
            const int ml = warpM * 32 + mt * 16 + gid + half * 8;
            if (ml >= mRem) continue;
            if (G1) {
                const size_t ob = (size_t)(off + m0 + ml) * HDIM + n0;
#pragma unroll
                for (int nt = 0; nt < 8; nt++) {
                    const int col = warpN * 64 + nt * 8 + tig * 2;
                    const float v0 = gelu_exact(acc[mt][nt][half * 2]     + sBias[col]);
                    const float v1 = gelu_exact(acc[mt][nt][half * 2 + 1] + sBias[col + 1]);
                    __half2 hp; hp.x = __float2half(v0); hp.y = __float2half(v1);
                    *(uint32_t*)(g_hh + ob + col) = *(uint32_t*)&hp;
                }
            } else {
                const int ent = g_idx[e * NTOK + m0 + ml];
                const float wgt = g_w[e * NTOK + m0 + ml];
                float* dst = outp + (size_t)(ent >> 1) * DDIM + n0;
#pragma unroll
                for (int nt = 0; nt < 8; nt++) {
                    const int col = warpN * 64 + nt * 8 + tig * 2;
                    atomicAdd(dst + col,     wgt * (acc[mt][nt][half * 2]     + sBias[col]));
                    atomicAdd(dst + col + 1, wgt * (acc[mt][nt][half * 2 + 1] + sBias[col + 1]));
                }
            }
        }
    }
}

// ---------------- launch ----------------
extern "C" void kernel_launch(void* const* d_in, const int* in_sizes, int n_in,
                              void* d_out, int out_size) {
    const float* x    = (const float*)d_in[0];
    const float* grad = (const float*)d_in[1];
    const float* Wr   = (const float*)d_in[2];
    const float* br   = (const float*)d_in[3];
    const float* W1   = (const float*)d_in[4];
    const float* b1   = (const float*)d_in[5];
    const float* W2   = (const float*)d_in[6];
    const float* b2   = (const float*)d_in[7];
    float* out   = (float*)d_out;
    float* probs = out + (size_t)NTOK * DDIM;

    const int SMEM_DYN = 49152;
    cudaFuncSetAttribute(moe_gemm_kernel<DDIM, true>,  cudaFuncAttributeMaxDynamicSharedMemorySize, SMEM_DYN);
    cudaFuncSetAttribute(moe_gemm_kernel<HDIM, false>, cudaFuncAttributeMaxDynamicSharedMemorySize, SMEM_DYN);

    zero_out_kernel<<<(NTOK * DDIM / 4) / 256, 256>>>(out);                       // 1
    prep_w_kernel<<<dim3(32, 8, 16), dim3(32, 32)>>>(W1, W2);                     // 2
    router_kernel<<<NTOK / 8, 256>>>(x, grad, Wr, br, probs);                     // 3
    moe_gemm_kernel<DDIM, true><<<dim3(HDIM / 128, NTOK / 128, EEXP), 256, SMEM_DYN>>>(b1, nullptr); // 4 (profiled)
    moe_gemm_kernel<HDIM, false><<<dim3(DDIM / 128, NTOK / 128, EEXP), 256, SMEM_DYN>>>(b2, out);    // 5
}